// round 7
// baseline (speedup 1.0000x reference)
#include <cuda_runtime.h>
#include <cuda_bf16.h>
#include <math.h>

// ---------------------------------------------------------------------------
// DeepDCNN: emb-gather -> 4x [grouped conv -> fold -> ordered top-k -> tanh] -> FC
// B=64, SEQ=1024, E=64, NC=6
// Layer i: Ghalf=[32,16,8,4], Cin/group=[1,10,14,18], NF=[10,14,18,22],
//          KS=[7,5,5,3], SOUT=Sin+KS-1, kpool=[768,512,256,4]
// ---------------------------------------------------------------------------

__device__ float g_bufA[21094400]; // max conv-out (layer0: 64*320*1030)
__device__ float g_bufB[15728640]; // max pooled   (layer0: 64*320*768)
__device__ float g_bufC[7340032];  // embed (4.19M) / pooled layer1 (7.34M)

// ---------------------------------------------------------------------------
// 1) Embedding gather + transpose via smem: X[b][e][s] = emb[tokens[b][s]][e]
// ---------------------------------------------------------------------------
__global__ __launch_bounds__(256)
void embed_kernel(const int* __restrict__ tokens,
                  const float* __restrict__ emb,
                  float* __restrict__ X)
{
    __shared__ float sm[64 * 65];
    __shared__ int stok[64];
    int blk = blockIdx.x;            // B * 16 blocks
    int b   = blk >> 4;
    int s0  = (blk & 15) << 6;
    int t   = threadIdx.x;

    if (t < 64) stok[t] = tokens[b * 1024 + s0 + t];
    __syncthreads();

    for (int i = t; i < 64 * 16; i += 256) {
        int r  = i >> 4;
        int c4 = i & 15;
        float4 v = *reinterpret_cast<const float4*>(emb + (long long)stok[r] * 64 + c4 * 4);
        float* d = &sm[r * 65 + c4 * 4];
        d[0] = v.x; d[1] = v.y; d[2] = v.z; d[3] = v.w;
    }
    __syncthreads();

    for (int i = t; i < 64 * 64; i += 256) {
        int e = i >> 6, s = i & 63;
        X[((long long)b * 64 + e) * 1024 + s0 + s] = sm[s * 65 + e];
    }
}

// ---------------------------------------------------------------------------
// 2) Fused grouped conv + bias + fold, packed f32x2 FMA, software-pipelined
//    window loads (next pc's window LDGs issue before current FMA block).
//    Weights relaid f-innermost in 16B-aligned smem -> packed broadcast LDS.64.
//    Each thread computes SPT consecutive s positions.
// ---------------------------------------------------------------------------
template<int CING, int NF, int KS, int THREADS, int SPT>
__global__ __launch_bounds__(THREADS)
void conv_fold_kernel(const float* __restrict__ x, const float* __restrict__ w,
                      const float* __restrict__ bias, float* __restrict__ y,
                      int SIN, int SOUT, int Ghalf, int stiles)
{
    constexpr int TS  = THREADS * SPT;
    constexpr int NFP = NF / 2;
    constexpr int WIN = KS + SPT - 1;    // window floats per (p,c)
    constexpr int PCN = 2 * CING;
    constexpr int WN  = 2 * NF * CING * KS;
    __shared__ __align__(16) float swT[WN];   // [p][c][j][f]

    int bid  = blockIdx.x;
    int tile = bid % stiles;
    int gp   = (bid / stiles) % Ghalf;
    int b    = bid / (stiles * Ghalf);
    int t    = threadIdx.x;
    int s0   = tile * TS;

    const int CH_IN  = Ghalf * 2 * CING;
    const int CH_OUT = Ghalf * NF;

    const float* wg = w + (long long)(2 * gp) * NF * CING * KS;
    for (int e = t; e < WN; e += THREADS) {
        int j  = e % KS;
        int r  = e / KS;
        int c  = r % CING;
        int r2 = r / CING;
        int f  = r2 % NF;
        int p  = r2 / NF;
        swT[((p * CING + c) * KS + j) * NF + f] = wg[e];
    }
    __syncthreads();

    int sbase = s0 + SPT * t;
    if (sbase >= SOUT) return;

    unsigned long long acc[NFP][SPT];
    #pragma unroll
    for (int fp = 0; fp < NFP; ++fp) {
        float blo = bias[2 * gp * NF + 2 * fp]     + bias[(2 * gp + 1) * NF + 2 * fp];
        float bhi = bias[2 * gp * NF + 2 * fp + 1] + bias[(2 * gp + 1) * NF + 2 * fp + 1];
        unsigned long long pb;
        asm("mov.b64 %0, {%1, %2};" : "=l"(pb)
            : "r"(__float_as_uint(blo)), "r"(__float_as_uint(bhi)));
        #pragma unroll
        for (int q = 0; q < SPT; ++q) acc[fp][q] = pb;
    }

    const float* xb = x + (long long)b * CH_IN * SIN + (long long)(2 * gp * CING) * SIN;
    int gbase = sbase - (KS - 1);

    // preload window for pc = 0
    float vbuf[WIN];
    #pragma unroll
    for (int i = 0; i < WIN; ++i) {
        int g = gbase + i;
        vbuf[i] = ((unsigned)g < (unsigned)SIN) ? __ldg(&xb[g]) : 0.f;
    }

    #pragma unroll 1
    for (int pc = 0; pc < PCN; ++pc) {
        // duplicate current window into f32x2 halves
        unsigned long long xd[WIN];
        #pragma unroll
        for (int i = 0; i < WIN; ++i)
            asm("mov.b64 %0, {%1, %1};" : "=l"(xd[i]) : "r"(__float_as_uint(vbuf[i])));
        // prefetch next pc's window (LDGs overlap following FMA block)
        if (pc + 1 < PCN) {
            const float* xr = xb + (long long)(pc + 1) * SIN;
            #pragma unroll
            for (int i = 0; i < WIN; ++i) {
                int g = gbase + i;
                vbuf[i] = ((unsigned)g < (unsigned)SIN) ? __ldg(&xr[g]) : 0.f;
            }
        }
        const float* wrow = &swT[pc * KS * NF];
        #pragma unroll
        for (int j = 0; j < KS; ++j) {
            #pragma unroll
            for (int fp = 0; fp < NFP; ++fp) {
                unsigned long long wp =
                    *reinterpret_cast<const unsigned long long*>(&wrow[j * NF + 2 * fp]);
                #pragma unroll
                for (int q = 0; q < SPT; ++q)
                    asm("fma.rn.f32x2 %0, %1, %2, %0;"
                        : "+l"(acc[fp][q]) : "l"(xd[j + q]), "l"(wp));
            }
        }
    }

    float* yb = y + (long long)b * CH_OUT * SOUT + (long long)gp * NF * SOUT;
    #pragma unroll
    for (int fp = 0; fp < NFP; ++fp) {
        #pragma unroll
        for (int q = 0; q < SPT; ++q) {
            int s = sbase + q;
            if (s < SOUT) {
                unsigned lo, hi;
                asm("mov.b64 {%0, %1}, %2;" : "=r"(lo), "=r"(hi) : "l"(acc[fp][q]));
                yb[(long long)(2 * fp)     * SOUT + s] = __uint_as_float(lo);
                yb[(long long)(2 * fp + 1) * SOUT + s] = __uint_as_float(hi);
            }
        }
    }
}

// ---------------------------------------------------------------------------
// 3) Ordered top-k + tanh per row, one 256-thread block per row.
// Pass 1: 8-bit MSB histogram over all n keys (warp-aggregated atomics,
// parallel suffix-scan select). Then COMPACT the indices of the selected
// bucket (order-free) and run the remaining 3 refinement passes over only
// those h candidates (h ~ n/256 typically). Finally stable compaction keeping
// keys > T plus first need_eq keys == T, fused with tanh.
// ---------------------------------------------------------------------------
__global__ __launch_bounds__(256)
void kmax_tanh_kernel(const float* __restrict__ x, float* __restrict__ y,
                      int n, int k)
{
    __shared__ unsigned skey[1032];
    __shared__ unsigned short cand[1032];
    __shared__ int hist[256];
    __shared__ int warpsum[8];
    __shared__ unsigned sh_dig, sh_krem, sh_done, sh_tot;
    __shared__ int sh_ncand;

    int row  = blockIdx.x;
    int t    = threadIdx.x;
    int lane = t & 31, wid = t >> 5;
    const float* xr = x + (long long)row * n;

    for (int i = t; i < n; i += 256) {
        unsigned u = __float_as_uint(xr[i]);
        skey[i] = (u & 0x80000000u) ? ~u : (u | 0x80000000u);
    }
    if (t == 0) { sh_done = 0; sh_ncand = 0; }
    __syncthreads();

    unsigned prefix = 0;
    int krem = k;

    // ---- pass 1: shift = 24, over all keys --------------------------------
    hist[t] = 0;
    __syncthreads();
    for (int base = 0; base < n; base += 256) {
        int i = base + t;
        bool ok = (i < n);
        unsigned key = ok ? skey[i] : 0u;
        unsigned ball = __ballot_sync(0xFFFFFFFFu, ok);
        if (ok) {
            int d = (int)(key >> 24);
            unsigned m = __match_any_sync(ball, d);
            if (lane == (__ffs(m) - 1))
                atomicAdd(&hist[d], __popc(m));
        }
    }
    __syncthreads();
    {   // parallel suffix-scan digit select
        int b = 255 - t;
        int h = hist[b];
        int v = h;
        #pragma unroll
        for (int off = 1; off < 32; off <<= 1) {
            int u = __shfl_up_sync(0xFFFFFFFFu, v, off);
            if (lane >= off) v += u;
        }
        if (lane == 31) warpsum[wid] = v;
        __syncthreads();
        if (t < 8) {
            int wv = warpsum[t];
            int vv = wv;
            #pragma unroll
            for (int off = 1; off < 8; off <<= 1) {
                int u = __shfl_up_sync(0xFFu, vv, off);
                if (t >= off) vv += u;
            }
            warpsum[t] = vv - wv;
        }
        __syncthreads();
        int suf = v + warpsum[wid];
        int cum = suf - h;
        if (suf >= krem && cum < krem) {
            sh_dig  = (unsigned)b;
            sh_krem = (unsigned)(krem - cum);
            if (h == krem - cum) sh_done = 1;   // whole bucket kept
        }
        __syncthreads();
    }
    prefix = sh_dig << 24;
    krem   = (int)sh_krem;
    __syncthreads();

    if (!sh_done) {
        // ---- compact candidate indices (order-free; only counts matter) ---
        unsigned bsel = prefix;   // top-8-bit pattern
        for (int base = 0; base < n; base += 256) {
            int i = base + t;
            if (i < n && (skey[i] & 0xFF000000u) == bsel) {
                int pos = atomicAdd(&sh_ncand, 1);
                cand[pos] = (unsigned short)i;
            }
        }
        __syncthreads();
        int hc = sh_ncand;

        // ---- passes 2..4 over candidates only -----------------------------
        for (int shift = 16; shift >= 0; shift -= 8) {
            if (sh_done) break;   // block-uniform
            hist[t] = 0;
            __syncthreads();
            unsigned hm = 0xFFFFFFFFu << (shift + 8);
            for (int base = 0; base < hc; base += 256) {
                int ci = base + t;
                bool ok = false;
                unsigned key = 0;
                if (ci < hc) { key = skey[cand[ci]]; ok = ((key & hm) == prefix); }
                unsigned ball = __ballot_sync(0xFFFFFFFFu, ok);
                if (ok) {
                    int d = (int)((key >> shift) & 255u);
                    unsigned m = __match_any_sync(ball, d);
                    if (lane == (__ffs(m) - 1))
                        atomicAdd(&hist[d], __popc(m));
                }
            }
            __syncthreads();
            {
                int b = 255 - t;
                int h = hist[b];
                int v = h;
                #pragma unroll
                for (int off = 1; off < 32; off <<= 1) {
                    int u = __shfl_up_sync(0xFFFFFFFFu, v, off);
                    if (lane >= off) v += u;
                }
                if (lane == 31) warpsum[wid] = v;
                __syncthreads();
                if (t < 8) {
                    int wv = warpsum[t];
                    int vv = wv;
                    #pragma unroll
                    for (int off = 1; off < 8; off <<= 1) {
                        int u = __shfl_up_sync(0xFFu, vv, off);
                        if (t >= off) vv += u;
                    }
                    warpsum[t] = vv - wv;
                }
                __syncthreads();
                int suf = v + warpsum[wid];
                int cum = suf - h;
                if (suf >= krem && cum < krem) {
                    sh_dig  = (unsigned)b;
                    sh_krem = (unsigned)(krem - cum);
                    if (h == krem - cum && shift > 0) sh_done = 1;
                }
                __syncthreads();
            }
            prefix |= (sh_dig << shift);
            krem = (int)sh_krem;
            __syncthreads();
        }
    }

    int need_eq = sh_done ? (n + 8) : krem;   // sh_done: keep every key == T
    const unsigned T = prefix;
    __syncthreads();

    // ---- stable compaction + tanh ----------------------------------------
    int carry_gt = 0, carry_eq = 0;
    for (int base = 0; base < n; base += 256) {
        int i = base + t;
        unsigned key = 0;
        int gt = 0, eq = 0;
        if (i < n) { key = skey[i]; gt = key > T; eq = key == T; }
        unsigned pk = ((unsigned)gt << 16) | (unsigned)eq;
        unsigned v2 = pk;
        #pragma unroll
        for (int off = 1; off < 32; off <<= 1) {
            unsigned u = __shfl_up_sync(0xFFFFFFFFu, v2, off);
            if (lane >= off) v2 += u;
        }
        if (lane == 31) warpsum[wid] = (int)v2;
        __syncthreads();
        if (t < 8) {
            unsigned wv = (unsigned)warpsum[t];
            unsigned vv = wv;
            #pragma unroll
            for (int off = 1; off < 8; off <<= 1) {
                unsigned u = __shfl_up_sync(0xFFu, vv, off);
                if (t >= off) vv += u;
            }
            warpsum[t] = (int)(vv - wv);
            if (t == 7) sh_tot = vv;
        }
        __syncthreads();
        unsigned excl = v2 - pk + (unsigned)warpsum[wid];
        int ggt = carry_gt + (int)(excl >> 16);
        int geq = carry_eq + (int)(excl & 0xFFFFu);
        if (i < n && (gt || (eq && geq < need_eq))) {
            int pos = ggt + min(geq, need_eq);
            float f = (key & 0x80000000u) ? __uint_as_float(key & 0x7FFFFFFFu)
                                          : __uint_as_float(~key);
            y[(long long)row * k + pos] = tanhf(f);
        }
        carry_gt += (int)(sh_tot >> 16);
        carry_eq += (int)(sh_tot & 0xFFFFu);
        __syncthreads();
    }
}

// ---------------------------------------------------------------------------
// 4) Final FC: out[b][n] = fcb[n] + sum_i x[b][i] * fcw[n][i],  i < 352
// ---------------------------------------------------------------------------
__global__ void fc_kernel(const float* __restrict__ x, const float* __restrict__ fcw,
                          const float* __restrict__ fcb, float* __restrict__ out)
{
    int t = blockIdx.x * blockDim.x + threadIdx.x;
    if (t >= 64 * 6) return;
    int b = t / 6, n = t % 6;
    const float* xr = x + b * 352;
    const float* wr = fcw + n * 352;
    float acc = fcb[n];
    #pragma unroll 4
    for (int i = 0; i < 352; ++i) acc = fmaf(xr[i], wr[i], acc);
    out[t] = acc;
}

// ---------------------------------------------------------------------------
extern "C" void kernel_launch(void* const* d_in, const int* in_sizes, int n_in,
                              void* d_out, int out_size)
{
    (void)in_sizes; (void)n_in; (void)out_size;
    const int*   tokens = (const int*)  d_in[0];
    const float* emb    = (const float*)d_in[1];
    const float* w1 = (const float*)d_in[2];
    const float* b1 = (const float*)d_in[3];
    const float* w2 = (const float*)d_in[4];
    const float* b2 = (const float*)d_in[5];
    const float* w3 = (const float*)d_in[6];
    const float* b3 = (const float*)d_in[7];
    const float* w4 = (const float*)d_in[8];
    const float* b4 = (const float*)d_in[9];
    const float* fcw = (const float*)d_in[10];
    const float* fcb = (const float*)d_in[11];
    float* out = (float*)d_out;

    float *A, *B_, *C;
    cudaGetSymbolAddress((void**)&A,  g_bufA);
    cudaGetSymbolAddress((void**)&B_, g_bufB);
    cudaGetSymbolAddress((void**)&C,  g_bufC);

    // embed: C = X (64, 64, 1024)
    embed_kernel<<<64 * 16, 256>>>(tokens, emb, C);

    // layer 0: Ghalf=32, Sin 1024 -> 1030, kpool 768  (TS=512, stiles=3)
    conv_fold_kernel<1, 10, 7, 128, 4><<<64 * 32 * 3, 128>>>(C, w1, b1, A, 1024, 1030, 32, 3);
    kmax_tanh_kernel<<<64 * 320, 256>>>(A, B_, 1030, 768);

    // layer 1: Ghalf=16, Sin 768 -> 772, kpool 512   (TS=512, stiles=2)
    conv_fold_kernel<10, 14, 5, 128, 4><<<64 * 16 * 2, 128>>>(B_, w2, b2, A, 768, 772, 16, 2);
    kmax_tanh_kernel<<<64 * 224, 256>>>(A, C, 772, 512);

    // layer 2: Ghalf=8, Sin 512 -> 516, kpool 256    (TS=256, stiles=3)
    conv_fold_kernel<14, 18, 5, 128, 2><<<64 * 8 * 3, 128>>>(C, w3, b3, A, 512, 516, 8, 3);
    kmax_tanh_kernel<<<64 * 144, 256>>>(A, B_, 516, 256);

    // layer 3: Ghalf=4, Sin 256 -> 258, kpool 4      (TS=256, stiles=2)
    conv_fold_kernel<18, 22, 3, 128, 2><<<64 * 4 * 2, 128>>>(B_, w4, b4, A, 256, 258, 4, 2);
    kmax_tanh_kernel<<<64 * 88, 256>>>(A, B_, 258, 4);

    // fc: (64, 352) @ (6, 352)^T + bias -> (64, 6)
    fc_kernel<<<3, 128>>>(B_, fcw, fcb, out);
}